// round 1
// baseline (speedup 1.0000x reference)
#include <cuda_runtime.h>
#include <math.h>

// Problem constants
#define R_TOTAL 131072          // B*N = 8*16384 flattened rows
#define DIMV    512
#define HEADS   8
#define DH      64
#define KR      4
#define BM      32              // rows per block

// Scratch (allocation-free rule: __device__ globals)
__device__ float g_q[(size_t)R_TOTAL * 32];   // q-hat, [row][h*4+r], 16 MB
__device__ float g_kv[16384];                 // [b][h][r][c] unnormalized then normalized
__device__ float g_ksum[256];                 // [b][h][r]

// ---------- packed f32x2 helpers (sm_10x FFMA2) ----------
__device__ __forceinline__ unsigned long long pack2f(float lo, float hi) {
    unsigned long long r;
    asm("mov.b64 %0, {%1,%2};" : "=l"(r) : "f"(lo), "f"(hi));
    return r;
}
__device__ __forceinline__ void unpack2f(unsigned long long v, float &lo, float &hi) {
    asm("mov.b64 {%0,%1}, %2;" : "=f"(lo), "=f"(hi) : "l"(v));
}
__device__ __forceinline__ void ffma2(unsigned long long &d, unsigned long long a, unsigned long long b) {
    asm("fma.rn.f32x2 %0, %1, %2, %0;" : "+l"(d) : "l"(a), "l"(b));
}

// ---------- zero the kv accumulators ----------
__global__ void k_zero() {
    int i = blockIdx.x * 256 + threadIdx.x;
    if (i < 16384) g_kv[i] = 0.0f;
    if (i < 256)   g_ksum[i] = 0.0f;
}

// ---------- kernel 1: x_mid GEMM + fused q/k/v epilogue + kv reduction ----------
// smem layout (floats):
//   xs   [0,       16384)  : 32x512 x tile; reused as vbuf in epilogue
//   ms   [16384,   32768)  : 32x512 x_mid tile
//   ws   [32768,   36864)  : 32x128 W_in tile; reused as W_v (64x64) in epilogue
//   eks  [36864,   37888)  : 32x32 exp(k) per row
//   wqk  [37888,   38400)  : W_q (256) then W_k (256)
#define SMEM1_FLOATS 38400

__global__ __launch_bounds__(256)
void k1(const float* __restrict__ x, const float* __restrict__ Win,
        const float* __restrict__ bin, const float* __restrict__ Wq,
        const float* __restrict__ Wk, const float* __restrict__ Wv)
{
    extern __shared__ float sm[];
    float* xs  = sm;
    float* ms  = sm + 16384;
    float* ws  = sm + 32768;
    float* eks = sm + 36864;
    float* wqk = sm + 37888;

    const int tid = threadIdx.x;
    const int br  = blockIdx.x;
    const float* xg = x + (size_t)br * BM * DIMV;

    // load x tile (32x512) into smem
    {
        const float4* src = (const float4*)xg;
        float4* dst = (float4*)xs;
        for (int i = tid; i < 4096; i += 256) dst[i] = src[i];
    }
    // load W_q / W_k (64x4 each)
    if (tid < 256) { wqk[tid] = Wq[tid]; wqk[256 + tid] = Wk[tid]; }
    __syncthreads();

    const int row = tid >> 3;     // 0..31
    const int cg  = tid & 7;      // 0..7, 16 cols each

    // GEMM: x_mid = x @ W_in + b_in, in 4 column chunks of 128
    for (int ch = 0; ch < 4; ch++) {
        const int c0 = ch * 128;
        unsigned long long acc[8];
        #pragma unroll
        for (int p = 0; p < 8; p++) acc[p] = 0ull;

        for (int k0 = 0; k0 < 512; k0 += 32) {
            // stage W_in[k0..k0+31][c0..c0+127] -> ws (32x128)
            for (int i = tid; i < 1024; i += 256) {
                int kk = i >> 5, c4 = i & 31;
                ((float4*)ws)[i] = *(const float4*)&Win[(size_t)(k0 + kk) * DIMV + c0 + c4 * 4];
            }
            __syncthreads();
            #pragma unroll
            for (int kk = 0; kk < 32; kk++) {
                float a = xs[row * DIMV + k0 + kk];
                unsigned long long a2 = pack2f(a, a);
                const ulonglong2* bp = (const ulonglong2*)(ws + kk * 128 + cg * 16);
                ulonglong2 b0 = bp[0], b1 = bp[1], b2 = bp[2], b3 = bp[3];
                ffma2(acc[0], a2, b0.x); ffma2(acc[1], a2, b0.y);
                ffma2(acc[2], a2, b1.x); ffma2(acc[3], a2, b1.y);
                ffma2(acc[4], a2, b2.x); ffma2(acc[5], a2, b2.y);
                ffma2(acc[6], a2, b3.x); ffma2(acc[7], a2, b3.y);
            }
            __syncthreads();
        }
        // bias + store x_mid chunk
        #pragma unroll
        for (int p = 0; p < 8; p++) {
            float lo, hi; unpack2f(acc[p], lo, hi);
            int c = c0 + cg * 16 + p * 2;
            ms[row * DIMV + c]     = lo + bin[c];
            ms[row * DIMV + c + 1] = hi + bin[c + 1];
        }
    }
    __syncthreads();

    // ---------------- epilogue: thread owns (row=erow, head=h) ----------------
    const int erow = tid >> 3;
    const int h    = tid & 7;

    // x_mid head slice into registers
    float xm[64];
    {
        const float* p = &ms[erow * DIMV + h * DH];
        #pragma unroll
        for (int d = 0; d < 64; d++) xm[d] = p[d];
    }

    // q / k logits (W_q, W_k broadcast across all threads)
    float ql[4] = {0.f, 0.f, 0.f, 0.f};
    float kl[4] = {0.f, 0.f, 0.f, 0.f};
    #pragma unroll
    for (int d = 0; d < 64; d++) {
        float a = xm[d];
        #pragma unroll
        for (int r = 0; r < 4; r++) {
            ql[r] += a * wqk[d * 4 + r];
            kl[r] += a * wqk[256 + d * 4 + r];
        }
    }
    // q softmax over r=4, store q-hat
    {
        float qm = fmaxf(fmaxf(ql[0], ql[1]), fmaxf(ql[2], ql[3]));
        float e0 = expf(ql[0] - qm), e1 = expf(ql[1] - qm);
        float e2 = expf(ql[2] - qm), e3 = expf(ql[3] - qm);
        float inv = 1.0f / (e0 + e1 + e2 + e3);
        size_t g = (size_t)br * BM + erow;
        g_q[g * 32 + h * 4 + 0] = e0 * inv;
        g_q[g * 32 + h * 4 + 1] = e1 * inv;
        g_q[g * 32 + h * 4 + 2] = e2 * inv;
        g_q[g * 32 + h * 4 + 3] = e3 * inv;
    }
    // exp(k) (no max-shift needed: |k| small) into smem
    eks[erow * 32 + h * 4 + 0] = expf(kl[0]);
    eks[erow * 32 + h * 4 + 1] = expf(kl[1]);
    eks[erow * 32 + h * 4 + 2] = expf(kl[2]);
    eks[erow * 32 + h * 4 + 3] = expf(kl[3]);

    // stage W_v (64x64) into ws (all prior ws readers passed a sync already)
    for (int i = tid; i < 1024; i += 256)
        ((float4*)ws)[i] = ((const float4*)Wv)[i];
    __syncthreads();

    // v = xm @ W_v -> vbuf (reuse xs)
    float* vbuf = xs;
    #pragma unroll
    for (int pass = 0; pass < 4; pass++) {
        unsigned long long vacc[8];
        #pragma unroll
        for (int p = 0; p < 8; p++) vacc[p] = 0ull;
        const int cb = pass * 16;
        #pragma unroll
        for (int d = 0; d < 64; d++) {
            unsigned long long a2 = pack2f(xm[d], xm[d]);
            const ulonglong2* wp = (const ulonglong2*)(ws + d * DH + cb);
            ulonglong2 w0 = wp[0], w1 = wp[1], w2 = wp[2], w3 = wp[3];
            ffma2(vacc[0], a2, w0.x); ffma2(vacc[1], a2, w0.y);
            ffma2(vacc[2], a2, w1.x); ffma2(vacc[3], a2, w1.y);
            ffma2(vacc[4], a2, w2.x); ffma2(vacc[5], a2, w2.y);
            ffma2(vacc[6], a2, w3.x); ffma2(vacc[7], a2, w3.y);
        }
        #pragma unroll
        for (int p = 0; p < 8; p++) {
            float lo, hi; unpack2f(vacc[p], lo, hi);
            vbuf[erow * DIMV + h * DH + cb + p * 2]     = lo;
            vbuf[erow * DIMV + h * DH + cb + p * 2 + 1] = hi;
        }
    }
    __syncthreads();

    // block-level kv partial reduction, then global atomic accumulate
    const int b = (br * BM) >> 14;   // batch index (16384 rows per batch)
    for (int o = tid; o < 2048; o += 256) {
        int hh = o >> 8, rr = (o >> 6) & 3, cc = o & 63;
        float s = 0.f;
        #pragma unroll
        for (int rw = 0; rw < 32; rw++)
            s += eks[rw * 32 + hh * 4 + rr] * vbuf[rw * DIMV + hh * DH + cc];
        atomicAdd(&g_kv[((b * 8 + hh) * 4 + rr) * 64 + cc], s);
    }
    if (tid < 32) {
        int hh = tid >> 2, rr = tid & 3;
        float s = 0.f;
        #pragma unroll
        for (int rw = 0; rw < 32; rw++) s += eks[rw * 32 + hh * 4 + rr];
        atomicAdd(&g_ksum[(b * 8 + hh) * 4 + rr], s);
    }
}

// ---------- kernel 2: normalize kv by column-softmax denominator ----------
__global__ void k_norm() {
    int i = blockIdx.x * 256 + threadIdx.x;
    if (i < 16384) g_kv[i] = g_kv[i] / g_ksum[i >> 6];
}

// ---------- kernel 3: qkv = q-hat @ kv, then out = qkv @ W_out + b_out ----------
// smem layout (floats):
//   qs  [0,     16384) : 32x512 qkv tile
//   ws  [16384, 20480) : 32x128 W_out tile
//   qh  [20480, 21504) : 32x32 q-hat
//   kvs [21504, 23552) : 8x4x64 kv for this batch
#define SMEM3_FLOATS 23552

__global__ __launch_bounds__(256)
void k3(const float* __restrict__ Wout, const float* __restrict__ bout,
        float* __restrict__ out)
{
    extern __shared__ float sm[];
    float* qs  = sm;
    float* ws  = sm + 16384;
    float* qh  = sm + 20480;
    float* kvs = sm + 21504;

    const int tid = threadIdx.x;
    const int br  = blockIdx.x;
    const int b   = (br * BM) >> 14;

    // load q-hat rows and this batch's kv
    {
        const float4* src = (const float4*)(g_q + (size_t)br * BM * 32);
        for (int i = tid; i < 256; i += 256) ((float4*)qh)[i] = src[i];
        const float4* kvsrc = (const float4*)(g_kv + b * 2048);
        for (int i = tid; i < 512; i += 256) ((float4*)kvs)[i] = kvsrc[i];
    }
    __syncthreads();

    // build qkv rows: thread owns (row, head)
    {
        const int row = tid >> 3, h = tid & 7;
        float q0 = qh[row * 32 + h * 4 + 0];
        float q1 = qh[row * 32 + h * 4 + 1];
        float q2 = qh[row * 32 + h * 4 + 2];
        float q3 = qh[row * 32 + h * 4 + 3];
        const float4* kp = (const float4*)kvs + (h * 4) * 16;
        #pragma unroll
        for (int c4 = 0; c4 < 16; c4++) {
            float4 a0 = kp[0 * 16 + c4], a1 = kp[1 * 16 + c4];
            float4 a2 = kp[2 * 16 + c4], a3 = kp[3 * 16 + c4];
            float4 o;
            o.x = q0 * a0.x + q1 * a1.x + q2 * a2.x + q3 * a3.x;
            o.y = q0 * a0.y + q1 * a1.y + q2 * a2.y + q3 * a3.y;
            o.z = q0 * a0.z + q1 * a1.z + q2 * a2.z + q3 * a3.z;
            o.w = q0 * a0.w + q1 * a1.w + q2 * a2.w + q3 * a3.w;
            ((float4*)qs)[row * 128 + h * 16 + c4] = o;
        }
    }
    __syncthreads();

    // GEMM: out = qs @ W_out + b_out
    const int row = tid >> 3;
    const int cg  = tid & 7;
    float* og = out + (size_t)br * BM * DIMV;

    for (int ch = 0; ch < 4; ch++) {
        const int c0 = ch * 128;
        unsigned long long acc[8];
        #pragma unroll
        for (int p = 0; p < 8; p++) acc[p] = 0ull;

        for (int k0 = 0; k0 < 512; k0 += 32) {
            for (int i = tid; i < 1024; i += 256) {
                int kk = i >> 5, c4 = i & 31;
                ((float4*)ws)[i] = *(const float4*)&Wout[(size_t)(k0 + kk) * DIMV + c0 + c4 * 4];
            }
            __syncthreads();
            #pragma unroll
            for (int kk = 0; kk < 32; kk++) {
                float a = qs[row * DIMV + k0 + kk];
                unsigned long long a2 = pack2f(a, a);
                const ulonglong2* bp = (const ulonglong2*)(ws + kk * 128 + cg * 16);
                ulonglong2 b0 = bp[0], b1 = bp[1], b2 = bp[2], b3 = bp[3];
                ffma2(acc[0], a2, b0.x); ffma2(acc[1], a2, b0.y);
                ffma2(acc[2], a2, b1.x); ffma2(acc[3], a2, b1.y);
                ffma2(acc[4], a2, b2.x); ffma2(acc[5], a2, b2.y);
                ffma2(acc[6], a2, b3.x); ffma2(acc[7], a2, b3.y);
            }
            __syncthreads();
        }
        #pragma unroll
        for (int p = 0; p < 8; p++) {
            float lo, hi; unpack2f(acc[p], lo, hi);
            int c = c0 + cg * 16 + p * 2;
            og[(size_t)row * DIMV + c]     = lo + bout[c];
            og[(size_t)row * DIMV + c + 1] = hi + bout[c + 1];
        }
    }
}

// ---------- launch ----------
extern "C" void kernel_launch(void* const* d_in, const int* in_sizes, int n_in,
                              void* d_out, int out_size)
{
    const float* x    = (const float*)d_in[0];
    const float* Win  = (const float*)d_in[1];
    const float* bin  = (const float*)d_in[2];
    const float* Wq   = (const float*)d_in[3];
    const float* Wk   = (const float*)d_in[4];
    const float* Wv   = (const float*)d_in[5];
    const float* Wout = (const float*)d_in[6];
    const float* bout = (const float*)d_in[7];
    float* out = (float*)d_out;

    cudaFuncSetAttribute(k1, cudaFuncAttributeMaxDynamicSharedMemorySize, SMEM1_FLOATS * 4);
    cudaFuncSetAttribute(k3, cudaFuncAttributeMaxDynamicSharedMemorySize, SMEM3_FLOATS * 4);

    const int nblocks = R_TOTAL / BM;   // 4096
    k_zero<<<64, 256>>>();
    k1<<<nblocks, 256, SMEM1_FLOATS * 4>>>(x, Win, bin, Wq, Wk, Wv);
    k_norm<<<64, 256>>>();
    k3<<<nblocks, 256, SMEM3_FLOATS * 4>>>(Wout, bout, out);
}

// round 2
// speedup vs baseline: 1.0566x; 1.0566x over previous
#include <cuda_runtime.h>
#include <math.h>

// Problem constants
#define R_TOTAL 131072          // B*N = 8*16384 flattened rows
#define DIMV    512
#define HEADS   8
#define DH      64
#define KR      4
#define BM      32              // rows per block

// Scratch (allocation-free rule: __device__ globals)
__device__ float g_q[(size_t)R_TOTAL * 32];   // q-hat, [row][h*4+r], 16 MB
__device__ float g_kv[16384];                 // [b][h][r][c] unnormalized then normalized
__device__ float g_ksum[256];                 // [b][h][r]

// ---------- packed f32x2 helpers (sm_10x FFMA2) ----------
__device__ __forceinline__ unsigned long long pack2f(float lo, float hi) {
    unsigned long long r;
    asm("mov.b64 %0, {%1,%2};" : "=l"(r) : "f"(lo), "f"(hi));
    return r;
}
__device__ __forceinline__ void unpack2f(unsigned long long v, float &lo, float &hi) {
    asm("mov.b64 {%0,%1}, %2;" : "=f"(lo), "=f"(hi) : "l"(v));
}
__device__ __forceinline__ void ffma2(unsigned long long &d, unsigned long long a, unsigned long long b) {
    asm("fma.rn.f32x2 %0, %1, %2, %0;" : "+l"(d) : "l"(a), "l"(b));
}

// ---------- zero the kv accumulators ----------
__global__ void k_zero() {
    int i = blockIdx.x * 256 + threadIdx.x;
    if (i < 16384) g_kv[i] = 0.0f;
    if (i < 256)   g_ksum[i] = 0.0f;
}

// ---------- kernel 1: x_mid GEMM + fused q/k/v epilogue + kv reduction ----------
// smem layout (floats):
//   xs   [0,       16384)  : 32x512 x tile; reused as vbuf in epilogue
//   ms   [16384,   32768)  : 32x512 x_mid tile
//   ws   [32768,   36864)  : 32x128 W_in tile; reused as W_v (64x64) in epilogue
//   eks  [36864,   37888)  : 32x32 exp(k) per row
//   wqk  [37888,   38400)  : W_q (256) then W_k (256)
#define SMEM1_FLOATS 38400

__global__ __launch_bounds__(256)
void k1(const float* __restrict__ x, const float* __restrict__ Win,
        const float* __restrict__ bin, const float* __restrict__ Wq,
        const float* __restrict__ Wk, const float* __restrict__ Wv)
{
    extern __shared__ float sm[];
    float* xs  = sm;
    float* ms  = sm + 16384;
    float* ws  = sm + 32768;
    float* eks = sm + 36864;
    float* wqk = sm + 37888;

    const int tid = threadIdx.x;
    const int br  = blockIdx.x;
    const float* xg = x + (size_t)br * BM * DIMV;

    // load x tile (32x512) into smem
    {
        const float4* src = (const float4*)xg;
        float4* dst = (float4*)xs;
        for (int i = tid; i < 4096; i += 256) dst[i] = src[i];
    }
    // load W_q / W_k (64x4 each)
    if (tid < 256) { wqk[tid] = Wq[tid]; wqk[256 + tid] = Wk[tid]; }
    __syncthreads();

    const int row = tid >> 3;     // 0..31
    const int cg  = tid & 7;      // 0..7, 16 cols each

    // GEMM: x_mid = x @ W_in + b_in, in 4 column chunks of 128
    for (int ch = 0; ch < 4; ch++) {
        const int c0 = ch * 128;
        unsigned long long acc[8];
        #pragma unroll
        for (int p = 0; p < 8; p++) acc[p] = 0ull;

        for (int k0 = 0; k0 < 512; k0 += 32) {
            // stage W_in[k0..k0+31][c0..c0+127] -> ws (32x128)
            for (int i = tid; i < 1024; i += 256) {
                int kk = i >> 5, c4 = i & 31;
                ((float4*)ws)[i] = *(const float4*)&Win[(size_t)(k0 + kk) * DIMV + c0 + c4 * 4];
            }
            __syncthreads();
            #pragma unroll
            for (int kk = 0; kk < 32; kk++) {
                float a = xs[row * DIMV + k0 + kk];
                unsigned long long a2 = pack2f(a, a);
                const ulonglong2* bp = (const ulonglong2*)(ws + kk * 128 + cg * 16);
                ulonglong2 b0 = bp[0], b1 = bp[1], b2 = bp[2], b3 = bp[3];
                ffma2(acc[0], a2, b0.x); ffma2(acc[1], a2, b0.y);
                ffma2(acc[2], a2, b1.x); ffma2(acc[3], a2, b1.y);
                ffma2(acc[4], a2, b2.x); ffma2(acc[5], a2, b2.y);
                ffma2(acc[6], a2, b3.x); ffma2(acc[7], a2, b3.y);
            }
            __syncthreads();
        }
        // bias + store x_mid chunk
        #pragma unroll
        for (int p = 0; p < 8; p++) {
            float lo, hi; unpack2f(acc[p], lo, hi);
            int c = c0 + cg * 16 + p * 2;
            ms[row * DIMV + c]     = lo + bin[c];
            ms[row * DIMV + c + 1] = hi + bin[c + 1];
        }
    }
    __syncthreads();

    // ---------------- epilogue: thread owns (row=erow, head=h) ----------------
    const int erow = tid >> 3;
    const int h    = tid & 7;

    // x_mid head slice into registers
    float xm[64];
    {
        const float* p = &ms[erow * DIMV + h * DH];
        #pragma unroll
        for (int d = 0; d < 64; d++) xm[d] = p[d];
    }

    // q / k logits (W_q, W_k broadcast across all threads)
    float ql[4] = {0.f, 0.f, 0.f, 0.f};
    float kl[4] = {0.f, 0.f, 0.f, 0.f};
    #pragma unroll
    for (int d = 0; d < 64; d++) {
        float a = xm[d];
        #pragma unroll
        for (int r = 0; r < 4; r++) {
            ql[r] += a * wqk[d * 4 + r];
            kl[r] += a * wqk[256 + d * 4 + r];
        }
    }
    // q softmax over r=4, store q-hat
    {
        float qm = fmaxf(fmaxf(ql[0], ql[1]), fmaxf(ql[2], ql[3]));
        float e0 = expf(ql[0] - qm), e1 = expf(ql[1] - qm);
        float e2 = expf(ql[2] - qm), e3 = expf(ql[3] - qm);
        float inv = 1.0f / (e0 + e1 + e2 + e3);
        size_t g = (size_t)br * BM + erow;
        g_q[g * 32 + h * 4 + 0] = e0 * inv;
        g_q[g * 32 + h * 4 + 1] = e1 * inv;
        g_q[g * 32 + h * 4 + 2] = e2 * inv;
        g_q[g * 32 + h * 4 + 3] = e3 * inv;
    }
    // exp(k) (no max-shift needed: |k| small) into smem
    eks[erow * 32 + h * 4 + 0] = expf(kl[0]);
    eks[erow * 32 + h * 4 + 1] = expf(kl[1]);
    eks[erow * 32 + h * 4 + 2] = expf(kl[2]);
    eks[erow * 32 + h * 4 + 3] = expf(kl[3]);

    // stage W_v (64x64) into ws (all prior ws readers passed a sync already)
    for (int i = tid; i < 1024; i += 256)
        ((float4*)ws)[i] = ((const float4*)Wv)[i];
    __syncthreads();

    // v = xm @ W_v -> vbuf (reuse xs)
    float* vbuf = xs;
    #pragma unroll
    for (int pass = 0; pass < 4; pass++) {
        unsigned long long vacc[8];
        #pragma unroll
        for (int p = 0; p < 8; p++) vacc[p] = 0ull;
        const int cb = pass * 16;
        #pragma unroll
        for (int d = 0; d < 64; d++) {
            unsigned long long a2 = pack2f(xm[d], xm[d]);
            const ulonglong2* wp = (const ulonglong2*)(ws + d * DH + cb);
            ulonglong2 w0 = wp[0], w1 = wp[1], w2 = wp[2], w3 = wp[3];
            ffma2(vacc[0], a2, w0.x); ffma2(vacc[1], a2, w0.y);
            ffma2(vacc[2], a2, w1.x); ffma2(vacc[3], a2, w1.y);
            ffma2(vacc[4], a2, w2.x); ffma2(vacc[5], a2, w2.y);
            ffma2(vacc[6], a2, w3.x); ffma2(vacc[7], a2, w3.y);
        }
        #pragma unroll
        for (int p = 0; p < 8; p++) {
            float lo, hi; unpack2f(vacc[p], lo, hi);
            vbuf[erow * DIMV + h * DH + cb + p * 2]     = lo;
            vbuf[erow * DIMV + h * DH + cb + p * 2 + 1] = hi;
        }
    }
    __syncthreads();

    // block-level kv partial reduction, then global atomic accumulate
    const int b = (br * BM) >> 14;   // batch index (16384 rows per batch)
    for (int o = tid; o < 2048; o += 256) {
        int hh = o >> 8, rr = (o >> 6) & 3, cc = o & 63;
        float s = 0.f;
        #pragma unroll
        for (int rw = 0; rw < 32; rw++)
            s += eks[rw * 32 + hh * 4 + rr] * vbuf[rw * DIMV + hh * DH + cc];
        atomicAdd(&g_kv[((b * 8 + hh) * 4 + rr) * 64 + cc], s);
    }
    if (tid < 32) {
        int hh = tid >> 2, rr = tid & 3;
        float s = 0.f;
        #pragma unroll
        for (int rw = 0; rw < 32; rw++) s += eks[rw * 32 + hh * 4 + rr];
        atomicAdd(&g_ksum[(b * 8 + hh) * 4 + rr], s);
    }
}

// ---------- kernel 2: normalize kv by column-softmax denominator ----------
__global__ void k_norm() {
    int i = blockIdx.x * 256 + threadIdx.x;
    if (i < 16384) g_kv[i] = g_kv[i] / g_ksum[i >> 6];
}

// ---------- kernel 3: qkv = q-hat @ kv, then out = qkv @ W_out + b_out ----------
// smem layout (floats):
//   qs  [0,     16384) : 32x512 qkv tile
//   ws  [16384, 20480) : 32x128 W_out tile
//   qh  [20480, 21504) : 32x32 q-hat
//   kvs [21504, 23552) : 8x4x64 kv for this batch
#define SMEM3_FLOATS 23552

__global__ __launch_bounds__(256)
void k3(const float* __restrict__ Wout, const float* __restrict__ bout,
        float* __restrict__ out)
{
    extern __shared__ float sm[];
    float* qs  = sm;
    float* ws  = sm + 16384;
    float* qh  = sm + 20480;
    float* kvs = sm + 21504;

    const int tid = threadIdx.x;
    const int br  = blockIdx.x;
    const int b   = (br * BM) >> 14;

    // load q-hat rows and this batch's kv
    {
        const float4* src = (const float4*)(g_q + (size_t)br * BM * 32);
        for (int i = tid; i < 256; i += 256) ((float4*)qh)[i] = src[i];
        const float4* kvsrc = (const float4*)(g_kv + b * 2048);
        for (int i = tid; i < 512; i += 256) ((float4*)kvs)[i] = kvsrc[i];
    }
    __syncthreads();

    // build qkv rows: thread owns (row, head)
    {
        const int row = tid >> 3, h = tid & 7;
        float q0 = qh[row * 32 + h * 4 + 0];
        float q1 = qh[row * 32 + h * 4 + 1];
        float q2 = qh[row * 32 + h * 4 + 2];
        float q3 = qh[row * 32 + h * 4 + 3];
        const float4* kp = (const float4*)kvs + (h * 4) * 16;
        #pragma unroll
        for (int c4 = 0; c4 < 16; c4++) {
            float4 a0 = kp[0 * 16 + c4], a1 = kp[1 * 16 + c4];
            float4 a2 = kp[2 * 16 + c4], a3 = kp[3 * 16 + c4];
            float4 o;
            o.x = q0 * a0.x + q1 * a1.x + q2 * a2.x + q3 * a3.x;
            o.y = q0 * a0.y + q1 * a1.y + q2 * a2.y + q3 * a3.y;
            o.z = q0 * a0.z + q1 * a1.z + q2 * a2.z + q3 * a3.z;
            o.w = q0 * a0.w + q1 * a1.w + q2 * a2.w + q3 * a3.w;
            ((float4*)qs)[row * 128 + h * 16 + c4] = o;
        }
    }
    __syncthreads();

    // GEMM: out = qs @ W_out + b_out
    const int row = tid >> 3;
    const int cg  = tid & 7;
    float* og = out + (size_t)br * BM * DIMV;

    for (int ch = 0; ch < 4; ch++) {
        const int c0 = ch * 128;
        unsigned long long acc[8];
        #pragma unroll
        for (int p = 0; p < 8; p++) acc[p] = 0ull;

        for (int k0 = 0; k0 < 512; k0 += 32) {
            for (int i = tid; i < 1024; i += 256) {
                int kk = i >> 5, c4 = i & 31;
                ((float4*)ws)[i] = *(const float4*)&Wout[(size_t)(k0 + kk) * DIMV + c0 + c4 * 4];
            }
            __syncthreads();
            #pragma unroll
            for (int kk = 0; kk < 32; kk++) {
                float a = qs[row * DIMV + k0 + kk];
                unsigned long long a2 = pack2f(a, a);
                const ulonglong2* bp = (const ulonglong2*)(ws + kk * 128 + cg * 16);
                ulonglong2 b0 = bp[0], b1 = bp[1], b2 = bp[2], b3 = bp[3];
                ffma2(acc[0], a2, b0.x); ffma2(acc[1], a2, b0.y);
                ffma2(acc[2], a2, b1.x); ffma2(acc[3], a2, b1.y);
                ffma2(acc[4], a2, b2.x); ffma2(acc[5], a2, b2.y);
                ffma2(acc[6], a2, b3.x); ffma2(acc[7], a2, b3.y);
            }
            __syncthreads();
        }
        #pragma unroll
        for (int p = 0; p < 8; p++) {
            float lo, hi; unpack2f(acc[p], lo, hi);
            int c = c0 + cg * 16 + p * 2;
            og[(size_t)row * DIMV + c]     = lo + bout[c];
            og[(size_t)row * DIMV + c + 1] = hi + bout[c + 1];
        }
    }
}

// ---------- launch ----------
extern "C" void kernel_launch(void* const* d_in, const int* in_sizes, int n_in,
                              void* d_out, int out_size)
{
    const float* x    = (const float*)d_in[0];
    const float* Win  = (const float*)d_in[1];
    const float* bin  = (const float*)d_in[2];
    const float* Wq   = (const float*)d_in[3];
    const float* Wk   = (const float*)d_in[4];
    const float* Wv   = (const float*)d_in[5];
    const float* Wout = (const float*)d_in[6];
    const float* bout = (const float*)d_in[7];
    float* out = (float*)d_out;

    cudaFuncSetAttribute(k1, cudaFuncAttributeMaxDynamicSharedMemorySize, SMEM1_FLOATS * 4);
    cudaFuncSetAttribute(k3, cudaFuncAttributeMaxDynamicSharedMemorySize, SMEM3_FLOATS * 4);

    const int nblocks = R_TOTAL / BM;   // 4096
    k_zero<<<64, 256>>>();
    k1<<<nblocks, 256, SMEM1_FLOATS * 4>>>(x, Win, bin, Wq, Wk, Wv);
    k_norm<<<64, 256>>>();
    k3<<<nblocks, 256, SMEM3_FLOATS * 4>>>(Wout, bout, out);
}